// round 7
// baseline (speedup 1.0000x reference)
#include <cuda_runtime.h>
#include <cuda_fp16.h>
#include <stdint.h>
#include <math.h>

#define BB 64
#define SS 4096
#define EE 50
#define TT 20
#define BBTT (BB * TT)

#define CS 128
#define HALO 5
#define RR 138              // positions p = 0..137, s = s0 - 5 + p
#define XROWS 148           // storage row = p + 1
#define XSTR 72             // halves per X row (144 B)
#define ASTR 72

// smem layout (bytes)
#define SM_A   0                        // 3 * 64 * 72 * 2 = 27648
#define SM_X   27648                    // 148 * 72 * 2    = 21312
#define SM_OW  (SM_X + XROWS*XSTR*2)    // 48960
#define SM_OB  (SM_OW + 4000)           // 52960
#define SM_CB  (SM_OB + 80)             // 53040 (64 floats)
#define SM_TRASH (SM_CB + 256)          // 53296 (16B aligned)
#define SMEM_TOTAL (SM_TRASH + 64)      // 53360

__device__ float g_em[(size_t)SS * BB * TT];
__device__ float g_ee[(size_t)(SS + 40) * BB * TT];
__device__ float g_num[BB];
__device__ float g_fvec[BB][TT];
__device__ float g_bvec[BB][TT];
__device__ float g_fL[BB];
__device__ float g_bL[BB];
__device__ float g_MB[BB][TT][TT];   // forward mid segment matrix, columns
__device__ float g_MBL[BB][TT];
__device__ float g_NC[BB][TT][TT];   // backward mid segment matrix, columns
__device__ float g_NCL[BB][TT];

__device__ __forceinline__ uint32_t smem_u32(const void* p) {
    uint32_t a;
    asm("{ .reg .u64 t; cvta.to.shared.u64 t, %1; cvt.u32.u64 %0, t; }" : "=r"(a) : "l"(p));
    return a;
}
__device__ __forceinline__ void ldsm_x4(uint32_t a, uint32_t r[4]) {
    asm volatile("ldmatrix.sync.aligned.m8n8.x4.shared.b16 {%0,%1,%2,%3}, [%4];"
                 : "=r"(r[0]), "=r"(r[1]), "=r"(r[2]), "=r"(r[3]) : "r"(a));
}
__device__ __forceinline__ void stsm_x2_t(uint32_t a, uint32_t r0, uint32_t r1) {
    asm volatile("stmatrix.sync.aligned.m8n8.x2.trans.shared.b16 [%0], {%1,%2};"
                 :: "r"(a), "r"(r0), "r"(r1) : "memory");
}
__device__ __forceinline__ void mma16816(float d[4], const uint32_t a[4], const uint32_t b[2]) {
    asm volatile("mma.sync.aligned.m16n8k16.row.col.f32.f16.f16.f32 "
                 "{%0,%1,%2,%3}, {%4,%5,%6,%7}, {%8,%9}, {%0,%1,%2,%3};"
                 : "+f"(d[0]), "+f"(d[1]), "+f"(d[2]), "+f"(d[3])
                 : "r"(a[0]), "r"(a[1]), "r"(a[2]), "r"(a[3]), "r"(b[0]), "r"(b[1]));
}
__device__ __forceinline__ uint32_t h2u(__half2 h) {
    return *reinterpret_cast<uint32_t*>(&h);
}

// ===========================================================================
// Conv stack on mma.sync. grid (32, 64), 256 threads = 8 warps.
// Residual kept in registers (half2 xh[9][2]); activation written back via
// stmatrix.trans (pad rows lane-redirected to a trash line). ldmatrix.x4 B.
// ===========================================================================
__global__ __launch_bounds__(256, 2)
void conv_emit_kernel(const int* __restrict__ token_id,
                      const float* __restrict__ embed_table,
                      const float* __restrict__ conv_w,
                      const float* __restrict__ conv_b,
                      const float* __restrict__ out_w,
                      const float* __restrict__ out_b)
{
    extern __shared__ char smem[];
    __half* Ah = (__half*)(smem + SM_A);
    __half* Xh = (__half*)(smem + SM_X);
    float*  ow = (float*)(smem + SM_OW);
    float*  ob = (float*)(smem + SM_OB);
    float*  cb = (float*)(smem + SM_CB);

    const int tid = threadIdx.x;
    const int b   = blockIdx.y;
    const int s0  = blockIdx.x * CS;

    // zero A + X regions
    for (int i = tid; i < SM_OW / 4; i += 256) ((uint32_t*)smem)[i] = 0u;
    __syncthreads();

    // A_kk[o][i] = conv_w[o][i][kk]
    for (int idx = tid; idx < 7500; idx += 256) {
        int o = idx / 150, rem = idx - o * 150;
        int i = rem / 3,   k = rem - i * 3;
        Ah[k * 64 * ASTR + o * ASTR + i] = __float2half(conv_w[idx]);
    }
    for (int i = tid; i < 1000; i += 256) ow[i] = out_w[i];
    if (tid < TT) ob[tid] = out_b[tid];
    if (tid < 64) cb[tid] = (tid < EE) ? conv_b[tid] : 0.0f;

    // embedding gather into X rows p+1
    for (int idx = tid; idx < RR * EE; idx += 256) {
        int p = idx / EE, e = idx - p * EE;
        int s = s0 - HALO + p;
        if (s >= 0 && s < SS) {
            int tok = token_id[b * SS + s];
            Xh[(p + 1) * XSTR + e] = __float2half(embed_table[tok * EE + e]);
        }
    }
    __syncthreads();

    const int lane = tid & 31, w = tid >> 5;
    const int m0 = (w & 3) * 16;
    const int n0base = (w >> 2) * 72;

    const uint32_t su = smem_u32(smem);
    const uint32_t Au = su + SM_A, Xu = su + SM_X;
    const uint32_t trash_u = su + SM_TRASH;

    // A fragments: 3 kk x 4 ksteps, resident for all layers
    uint32_t af[12][4];
    {
        const int arow  = m0 + (lane & 15);
        const int acolh = 8 * (lane >> 4);
        #pragma unroll
        for (int kk = 0; kk < 3; ++kk)
            #pragma unroll
            for (int ks = 0; ks < 4; ++ks)
                ldsm_x4(Au + kk * (64 * ASTR * 2) + arow * (ASTR * 2)
                           + (16 * ks + acolh) * 2, af[kk * 4 + ks]);
    }

    const int pad_lo = (s0 == 0) ? HALO : 0;
    int seq_hi = SS - s0 + HALO; if (seq_hi > RR) seq_hi = RR;
    const int gid = lane >> 2, tig = lane & 3;
    const int o0 = m0 + gid, o1 = o0 + 8;
    const float cb0 = cb[o0], cb1 = cb[o1];
    const int brow = lane & 7;
    const int col8 = 8 * (lane >> 3);     // 0,8,16,24 for ldmatrix.x4

    // residual registers: xh[nt][0] = (x[o0,pA], x[o0,pA+1]); [1] = o1 block
    __half2 xh[9][2];
    #pragma unroll
    for (int nt = 0; nt < 9; ++nt) {
        int pA = n0base + nt * 8 + 2 * tig;
        xh[nt][0] = __halves2half2(Xh[(pA + 1) * XSTR + o0], Xh[(pA + 2) * XSTR + o0]);
        xh[nt][1] = __halves2half2(Xh[(pA + 1) * XSTR + o1], Xh[(pA + 2) * XSTR + o1]);
    }

    #pragma unroll 1
    for (int l = 1; l <= 5; ++l) {
        #pragma unroll
        for (int nt0 = 0; nt0 < 9; nt0 += 2) {
            float acc0[4] = {0.f, 0.f, 0.f, 0.f};
            float acc1[4] = {0.f, 0.f, 0.f, 0.f};
            const bool two = (nt0 + 1 < 9);
            #pragma unroll
            for (int kk = 0; kk < 3; ++kk)
                #pragma unroll
                for (int ks = 0; ks < 4; ks += 2) {
                    uint32_t base = Xu + (n0base + brow + kk) * (XSTR * 2)
                                       + (16 * ks + col8) * 2;
                    uint32_t bf[4];
                    ldsm_x4(base + nt0 * (8 * XSTR * 2), bf);
                    mma16816(acc0, af[kk * 4 + ks],     bf);
                    mma16816(acc0, af[kk * 4 + ks + 1], bf + 2);
                    if (two) {
                        uint32_t bg[4];
                        ldsm_x4(base + (nt0 + 1) * (8 * XSTR * 2), bg);
                        mma16816(acc1, af[kk * 4 + ks],     bg);
                        mma16816(acc1, af[kk * 4 + ks + 1], bg + 2);
                    }
                }
            // swish + residual, pure registers
            {
                float y0 = acc0[0] + cb0, y1 = acc0[1] + cb0;
                float y2 = acc0[2] + cb1, y3 = acc0[3] + cb1;
                float nx0 = __low2float(xh[nt0][0])  + __fdividef(y0, 1.f + __expf(-y0));
                float nx1 = __high2float(xh[nt0][0]) + __fdividef(y1, 1.f + __expf(-y1));
                float nx2 = __low2float(xh[nt0][1])  + __fdividef(y2, 1.f + __expf(-y2));
                float nx3 = __high2float(xh[nt0][1]) + __fdividef(y3, 1.f + __expf(-y3));
                xh[nt0][0] = __floats2half2_rn(nx0, nx1);
                xh[nt0][1] = __floats2half2_rn(nx2, nx3);
            }
            if (two) {
                float y0 = acc1[0] + cb0, y1 = acc1[1] + cb0;
                float y2 = acc1[2] + cb1, y3 = acc1[3] + cb1;
                float nx0 = __low2float(xh[nt0+1][0])  + __fdividef(y0, 1.f + __expf(-y0));
                float nx1 = __high2float(xh[nt0+1][0]) + __fdividef(y1, 1.f + __expf(-y1));
                float nx2 = __low2float(xh[nt0+1][1])  + __fdividef(y2, 1.f + __expf(-y2));
                float nx3 = __high2float(xh[nt0+1][1]) + __fdividef(y3, 1.f + __expf(-y3));
                xh[nt0+1][0] = __floats2half2_rn(nx0, nx1);
                xh[nt0+1][1] = __floats2half2_rn(nx2, nx3);
            }
        }
        __syncthreads();   // all ldmatrix reads done before X overwritten

        #pragma unroll
        for (int nt = 0; nt < 9; ++nt) {
            int pr = n0base + nt * 8 + (lane & 7);
            uint32_t addr = (pr >= pad_lo && pr < seq_hi)
                ? (Xu + (pr + 1) * (XSTR * 2) + (m0 + ((lane >> 3) & 1) * 8) * 2)
                : trash_u;
            stsm_x2_t(addr, h2u(xh[nt][0]), h2u(xh[nt][1]));
        }
        __syncthreads();   // X updated before next layer / emissions
    }

    // emissions
    for (int idx = tid; idx < TT * CS; idx += 256) {
        int t = idx % TT;
        int q = idx / TT;
        int s = s0 + q;
        const __half* xr = &Xh[(q + HALO + 1) * XSTR];
        float acc = ob[t];
        const float* owt = &ow[t * EE];
        #pragma unroll 5
        for (int e = 0; e < EE; ++e) acc = fmaf(__half2float(xr[e]), owt[e], acc);
        int gi = (s * BB + b) * TT + t;
        g_em[gi] = acc;
        g_ee[gi] = __expf(acc);
    }
}

// ===========================================================================
// CRF, 4-way split. grid (BB, 43) x 32:
//   role 0: alpha vector scan t=1..1024
//   role 1: beta  vector scan t=4095..3073 (1023 steps)
//   role 2: numerator
//   role 3..22:  column c of M_B (ops t=1025..2048, forward orientation)
//   role 23..42: column c of N   (ops t=3072..2049, backward orientation)
// ===========================================================================
__device__ __forceinline__ float crf_dot(float c, const float* E)
{
    float a0 = 0.f, a1 = 0.f, a2 = 0.f, a3 = 0.f;
    #pragma unroll
    for (int i = 0; i < TT; i += 4) {
        a0 = fmaf(__shfl_sync(0xffffffffu, c, i + 0), E[i + 0], a0);
        a1 = fmaf(__shfl_sync(0xffffffffu, c, i + 1), E[i + 1], a1);
        a2 = fmaf(__shfl_sync(0xffffffffu, c, i + 2), E[i + 2], a2);
        a3 = fmaf(__shfl_sync(0xffffffffu, c, i + 3), E[i + 3], a3);
    }
    return (a0 + a1) + (a2 + a3);
}

template<int NSTEPS, bool POST>
__device__ __forceinline__ void scan_run(const float* p, int stride,
                                         float& vio, float& Lio, const float* E)
{
    float v = vio, L = Lio;
    float ea[8], eb[8], rinv = 1.0f, lg = 0.0f, m;
    #pragma unroll
    for (int k = 0; k < 8; ++k) ea[k] = p[k * stride];
    for (int g = 0; g < 128; g += 2) {
        const float* p1 = p + (g + 1) * 8 * stride;
        #pragma unroll
        for (int k = 0; k < 8; ++k) eb[k] = p1[k * stride];
        #pragma unroll
        for (int k = 0; k < 8; ++k)
            if (g * 8 + k < NSTEPS)
                v = POST ? ea[k] * crf_dot(v, E) : crf_dot(ea[k] * v, E);
        v *= rinv; L += lg;
        m = __shfl_sync(0xffffffffu, v, 0);
        rinv = __frcp_rn(m); lg = __log2f(m);
        const float* p2 = p + (g + 2) * 8 * stride;
        #pragma unroll
        for (int k = 0; k < 8; ++k) ea[k] = p2[k * stride];
        #pragma unroll
        for (int k = 0; k < 8; ++k)
            if ((g + 1) * 8 + k < NSTEPS)
                v = POST ? eb[k] * crf_dot(v, E) : crf_dot(eb[k] * v, E);
        v *= rinv; L += lg;
        m = __shfl_sync(0xffffffffu, v, 0);
        rinv = __frcp_rn(m); lg = __log2f(m);
    }
    v *= rinv; L += lg;
    vio = v; Lio = L;
}

__global__ void crf_kernel(const int* __restrict__ tag,
                           const float* __restrict__ start_trans,
                           const float* __restrict__ end_trans,
                           const float* __restrict__ trans)
{
    const int b = blockIdx.x;
    const int role = blockIdx.y;
    const int j = threadIdx.x;
    const bool ok = (j < TT);
    const int jj = ok ? j : 0;

    if (role == 2) {
        float sum = 0.0f;
        for (int s = j; s < SS; s += 32) {
            int tg = tag[b * SS + s];
            sum += g_em[(s * BB + b) * TT + tg];
            if (s > 0)      sum += trans[tag[b * SS + s - 1] * TT + tg];
            if (s == 0)     sum += start_trans[tg];
            if (s == SS-1)  sum += end_trans[tg];
        }
        #pragma unroll
        for (int o = 16; o > 0; o >>= 1) sum += __shfl_xor_sync(0xffffffffu, sum, o);
        if (j == 0) g_num[b] = sum;
        return;
    }

    float E[TT];
    float val, L = 0.0f;
    const float* base = g_ee + b * TT + jj;   // + t*BBTT

    if (role == 0) {
        #pragma unroll
        for (int i = 0; i < TT; ++i) E[i] = ok ? __expf(trans[i * TT + jj]) : 0.0f;
        val = ok ? __expf(start_trans[jj]) * base[0] : 0.0f;
        scan_run<1024, true>(base + 1 * BBTT, BBTT, val, L, E);
        if (ok) g_fvec[b][jj] = val;
        if (j == 0) g_fL[b] = L;
    } else if (role == 1) {
        #pragma unroll
        for (int i = 0; i < TT; ++i) E[i] = ok ? __expf(trans[jj * TT + i]) : 0.0f;
        val = ok ? __expf(end_trans[jj]) : 0.0f;
        scan_run<1023, false>(base + 4095 * BBTT, -BBTT, val, L, E);
        if (ok) g_bvec[b][jj] = val;
        if (j == 0) g_bL[b] = L;
    } else if (role < 23) {
        int c = role - 3;
        #pragma unroll
        for (int i = 0; i < TT; ++i) E[i] = ok ? __expf(trans[i * TT + jj]) : 0.0f;
        val = (ok && jj == c) ? 1.0f : 0.0f;
        scan_run<1024, true>(base + 1025 * BBTT, BBTT, val, L, E);
        if (ok) g_MB[b][c][jj] = val;
        if (j == 0) g_MBL[b][c] = L;
    } else {
        int c = role - 23;
        #pragma unroll
        for (int i = 0; i < TT; ++i) E[i] = ok ? __expf(trans[jj * TT + i]) : 0.0f;
        val = (ok && jj == c) ? 1.0f : 0.0f;
        scan_run<1024, false>(base + 3072 * BBTT, -BBTT, val, L, E);
        if (ok) g_NC[b][c][jj] = val;
        if (j == 0) g_NCL[b][c] = L;
    }
}

// ===========================================================================
// Combine: alpha_2048 = M_B alpha_1024; beta_2048 = N beta_3072;
// den = ln2*(La + Lm + Lb + Ln) + log(alpha_2048 . beta_2048)
// ===========================================================================
__global__ void final_kernel(float* __restrict__ out)
{
    __shared__ float red[64];
    int b = threadIdx.x;

    float Lm = -1e30f, Ln = -1e30f;
    #pragma unroll
    for (int c = 0; c < TT; ++c) {
        Lm = fmaxf(Lm, g_MBL[b][c]);
        Ln = fmaxf(Ln, g_NCL[b][c]);
    }
    float u[TT], v[TT];
    #pragma unroll
    for (int t = 0; t < TT; ++t) { u[t] = 0.0f; v[t] = 0.0f; }
    for (int c = 0; c < TT; ++c) {
        float sa = g_fvec[b][c] * exp2f(g_MBL[b][c] - Lm);
        float sb = g_bvec[b][c] * exp2f(g_NCL[b][c] - Ln);
        #pragma unroll
        for (int t = 0; t < TT; ++t) {
            u[t] = fmaf(g_MB[b][c][t], sa, u[t]);
            v[t] = fmaf(g_NC[b][c][t], sb, v[t]);
        }
    }
    float s = 0.0f;
    #pragma unroll
    for (int t = 0; t < TT; ++t) s = fmaf(u[t], v[t], s);
    float den = 0.69314718055994531f * (g_fL[b] + Lm + g_bL[b] + Ln) + logf(s);
    red[b] = den - g_num[b];
    __syncthreads();
    for (int k = 32; k > 0; k >>= 1) {
        if (b < k) red[b] += red[b + k];
        __syncthreads();
    }
    if (b == 0) out[0] = red[0];
}

extern "C" void kernel_launch(void* const* d_in, const int* in_sizes, int n_in,
                              void* d_out, int out_size)
{
    const int*   token_id    = (const int*)d_in[0];
    const int*   tag_id      = (const int*)d_in[1];
    const float* embed_table = (const float*)d_in[2];
    const float* conv_w      = (const float*)d_in[3];
    const float* conv_b      = (const float*)d_in[4];
    const float* out_w       = (const float*)d_in[5];
    const float* out_b       = (const float*)d_in[6];
    const float* start_trans = (const float*)d_in[7];
    const float* end_trans   = (const float*)d_in[8];
    const float* trans       = (const float*)d_in[9];

    cudaFuncSetAttribute(conv_emit_kernel,
                         cudaFuncAttributeMaxDynamicSharedMemorySize, SMEM_TOTAL);

    dim3 grid(SS / CS, BB);
    conv_emit_kernel<<<grid, 256, SMEM_TOTAL>>>(token_id, embed_table, conv_w,
                                                conv_b, out_w, out_b);
    crf_kernel<<<dim3(BB, 43), 32>>>(tag_id, start_trans, end_trans, trans);
    final_kernel<<<1, 64>>>((float*)d_out);
}

// round 9
// speedup vs baseline: 1.1677x; 1.1677x over previous
#include <cuda_runtime.h>
#include <cuda_fp16.h>
#include <stdint.h>
#include <math.h>

#define BB 64
#define SS 4096
#define EE 50
#define TT 20

#define CS 128
#define HALO 5
#define RR 138              // positions p = 0..137, s = s0 - 5 + p
#define ASTR 72

// X tiled layout: rows 0..151 (19 row-tiles), cols 0..63 (8 col-tiles)
// addr(row,col) = ((row>>3)*8 + (col>>3))*128 + (row&7)*16 + (col&7)*2
#define XT(row, col) (((((row) >> 3) * 8 + ((col) >> 3)) << 7) + (((row) & 7) << 4) + (((col) & 7) << 1))

// smem layout (bytes)
#define SM_A   0                        // 3 * 64 * 72 * 2 = 27648
#define SM_X   27648                    // 19 * 8 * 128    = 19456
#define SM_OW  (SM_X + 19456)           // 47104
#define SM_OB  (SM_OW + 4000)           // 51104
#define SM_CB  (SM_OB + 80)             // 51184
#define SM_TRASH (SM_CB + 256)          // 51440 (16B aligned)
#define SMEM_TOTAL (SM_TRASH + 64)

__device__ float g_em[(size_t)SS * BB * TT];
__device__ float g_ee[(size_t)(SS + 40) * BB * TT];
__device__ float g_num[BB];
__device__ float g_fvec[BB][TT];
__device__ float g_bvec[BB][TT];
__device__ float g_fL[BB];
__device__ float g_bL[BB];

__device__ __forceinline__ uint32_t smem_u32(const void* p) {
    uint32_t a;
    asm("{ .reg .u64 t; cvta.to.shared.u64 t, %1; cvt.u32.u64 %0, t; }" : "=r"(a) : "l"(p));
    return a;
}
__device__ __forceinline__ void ldsm_x4(uint32_t a, uint32_t r[4]) {
    asm volatile("ldmatrix.sync.aligned.m8n8.x4.shared.b16 {%0,%1,%2,%3}, [%4];"
                 : "=r"(r[0]), "=r"(r[1]), "=r"(r[2]), "=r"(r[3]) : "r"(a));
}
__device__ __forceinline__ void stsm_x2_t(uint32_t a, uint32_t r0, uint32_t r1) {
    asm volatile("stmatrix.sync.aligned.m8n8.x2.trans.shared.b16 [%0], {%1,%2};"
                 :: "r"(a), "r"(r0), "r"(r1) : "memory");
}
__device__ __forceinline__ void mma16816(float d[4], const uint32_t a[4], const uint32_t b[2]) {
    asm volatile("mma.sync.aligned.m16n8k16.row.col.f32.f16.f16.f32 "
                 "{%0,%1,%2,%3}, {%4,%5,%6,%7}, {%8,%9}, {%0,%1,%2,%3};"
                 : "+f"(d[0]), "+f"(d[1]), "+f"(d[2]), "+f"(d[3])
                 : "r"(a[0]), "r"(a[1]), "r"(a[2]), "r"(a[3]), "r"(b[0]), "r"(b[1]));
}
__device__ __forceinline__ uint32_t h2u(__half2 h) {
    return *reinterpret_cast<uint32_t*>(&h);
}

// ===========================================================================
// Conv stack on mma.sync, X in 8x8 tiled smem (1 line per ldmatrix tile).
// grid (32, 64), 256 threads = 8 warps: warp w -> m-tile (w&3), n-half (w>>2)
// Residual in registers; writeback via stmatrix.trans (pad rows -> trash).
// FIX vs R8: B-load row = n0base + lane7 + kk (tap -1 and storage +1 cancel).
// ===========================================================================
__global__ __launch_bounds__(256, 2)
void conv_emit_kernel(const int* __restrict__ token_id,
                      const float* __restrict__ embed_table,
                      const float* __restrict__ conv_w,
                      const float* __restrict__ conv_b,
                      const float* __restrict__ out_w,
                      const float* __restrict__ out_b)
{
    extern __shared__ char smem[];
    __half* Ah = (__half*)(smem + SM_A);
    float*  ow = (float*)(smem + SM_OW);
    float*  ob = (float*)(smem + SM_OB);
    float*  cb = (float*)(smem + SM_CB);

    const int tid = threadIdx.x;
    const int b   = blockIdx.y;
    const int s0  = blockIdx.x * CS;

    // zero A + X regions
    for (int i = tid; i < SM_OW / 4; i += 256) ((uint32_t*)smem)[i] = 0u;
    __syncthreads();

    // A_kk[o][i] = conv_w[o][i][kk]  (linear layout, loaded to regs once)
    for (int idx = tid; idx < 7500; idx += 256) {
        int o = idx / 150, rem = idx - o * 150;
        int i = rem / 3,   k = rem - i * 3;
        Ah[k * 64 * ASTR + o * ASTR + i] = __float2half(conv_w[idx]);
    }
    for (int i = tid; i < 1000; i += 256) ow[i] = out_w[i];
    if (tid < TT) ob[tid] = out_b[tid];
    if (tid < 64) cb[tid] = (tid < EE) ? conv_b[tid] : 0.0f;

    // embedding gather into tiled X (storage row = p + 1)
    for (int idx = tid; idx < RR * EE; idx += 256) {
        int p = idx / EE, e = idx - p * EE;
        int s = s0 - HALO + p;
        if (s >= 0 && s < SS) {
            int tok = token_id[b * SS + s];
            *(__half*)(smem + SM_X + XT(p + 1, e)) = __float2half(embed_table[tok * EE + e]);
        }
    }
    __syncthreads();

    const int lane = tid & 31, w = tid >> 5;
    const int m0 = (w & 3) * 16;
    const int n0base = (w >> 2) * 72;

    const uint32_t su = smem_u32(smem);
    const uint32_t Au = su + SM_A, XBu = su + SM_X;
    const uint32_t trash_u = su + SM_TRASH;

    // A fragments: 3 kk x 4 ksteps, resident for all layers
    uint32_t af[12][4];
    {
        const int arow  = m0 + (lane & 15);
        const int acolh = 8 * (lane >> 4);
        #pragma unroll
        for (int kk = 0; kk < 3; ++kk)
            #pragma unroll
            for (int ks = 0; ks < 4; ++ks)
                ldsm_x4(Au + kk * (64 * ASTR * 2) + arow * (ASTR * 2)
                           + (16 * ks + acolh) * 2, af[kk * 4 + ks]);
    }

    const int pad_lo = (s0 == 0) ? HALO : 0;
    int seq_hi = SS - s0 + HALO; if (seq_hi > RR) seq_hi = RR;
    const int gid = lane >> 2, tig = lane & 3;
    const int o0 = m0 + gid, o1 = o0 + 8;
    const float cb0 = cb[o0], cb1 = cb[o1];
    const int lane7 = lane & 7;
    const int g8    = lane >> 3;       // 0..3 -> k col-tile for ldmatrix.x4

    // per-kk lane-constant B load base: storage row = n0base + lane7 + kk
    // (output position p = n0base + 8nt + lane7 needs x[p+kk-1] = storage row p+kk)
    uint32_t bbase[3];
    #pragma unroll
    for (int kk = 0; kk < 3; ++kk) {
        int row_l = n0base + lane7 + kk;
        bbase[kk] = XBu + (row_l >> 3) * 1024 + (row_l & 7) * 16 + g8 * 128;
    }
    // stmatrix base (lane-constant): storage row = n0base + lane7 + 1, col tile
    const int strow = n0base + lane7 + 1;
    const uint32_t stbase = XBu + (strow >> 3) * 1024 + (strow & 7) * 16
                               + (2 * (w & 3) + ((lane >> 3) & 1)) * 128;
    const int pr0 = n0base + lane7;

    // residual registers
    __half2 xh[9][2];
    #pragma unroll
    for (int nt = 0; nt < 9; ++nt) {
        int pA = n0base + nt * 8 + 2 * tig;
        xh[nt][0] = __halves2half2(*(__half*)(smem + SM_X + XT(pA + 1, o0)),
                                   *(__half*)(smem + SM_X + XT(pA + 2, o0)));
        xh[nt][1] = __halves2half2(*(__half*)(smem + SM_X + XT(pA + 1, o1)),
                                   *(__half*)(smem + SM_X + XT(pA + 2, o1)));
    }

    #pragma unroll 1
    for (int l = 1; l <= 5; ++l) {
        #pragma unroll
        for (int nt0 = 0; nt0 < 9; nt0 += 2) {
            float acc0[4] = {0.f, 0.f, 0.f, 0.f};
            float acc1[4] = {0.f, 0.f, 0.f, 0.f};
            const bool two = (nt0 + 1 < 9);
            #pragma unroll
            for (int kk = 0; kk < 3; ++kk)
                #pragma unroll
                for (int ksp = 0; ksp < 2; ++ksp) {
                    uint32_t base = bbase[kk] + ksp * 512;
                    uint32_t bf[4];
                    ldsm_x4(base + nt0 * 1024, bf);
                    mma16816(acc0, af[kk * 4 + 2 * ksp],     bf);
                    mma16816(acc0, af[kk * 4 + 2 * ksp + 1], bf + 2);
                    if (two) {
                        uint32_t bg[4];
                        ldsm_x4(base + (nt0 + 1) * 1024, bg);
                        mma16816(acc1, af[kk * 4 + 2 * ksp],     bg);
                        mma16816(acc1, af[kk * 4 + 2 * ksp + 1], bg + 2);
                    }
                }
            {
                float y0 = acc0[0] + cb0, y1 = acc0[1] + cb0;
                float y2 = acc0[2] + cb1, y3 = acc0[3] + cb1;
                float nx0 = __low2float(xh[nt0][0])  + __fdividef(y0, 1.f + __expf(-y0));
                float nx1 = __high2float(xh[nt0][0]) + __fdividef(y1, 1.f + __expf(-y1));
                float nx2 = __low2float(xh[nt0][1])  + __fdividef(y2, 1.f + __expf(-y2));
                float nx3 = __high2float(xh[nt0][1]) + __fdividef(y3, 1.f + __expf(-y3));
                xh[nt0][0] = __floats2half2_rn(nx0, nx1);
                xh[nt0][1] = __floats2half2_rn(nx2, nx3);
            }
            if (two) {
                float y0 = acc1[0] + cb0, y1 = acc1[1] + cb0;
                float y2 = acc1[2] + cb1, y3 = acc1[3] + cb1;
                float nx0 = __low2float(xh[nt0+1][0])  + __fdividef(y0, 1.f + __expf(-y0));
                float nx1 = __high2float(xh[nt0+1][0]) + __fdividef(y1, 1.f + __expf(-y1));
                float nx2 = __low2float(xh[nt0+1][1])  + __fdividef(y2, 1.f + __expf(-y2));
                float nx3 = __high2float(xh[nt0+1][1]) + __fdividef(y3, 1.f + __expf(-y3));
                xh[nt0+1][0] = __floats2half2_rn(nx0, nx1);
                xh[nt0+1][1] = __floats2half2_rn(nx2, nx3);
            }
        }
        __syncthreads();   // ldmatrix reads done before X overwritten

        #pragma unroll
        for (int nt = 0; nt < 9; ++nt) {
            int pr = pr0 + 8 * nt;
            uint32_t addr = (pr >= pad_lo && pr < seq_hi) ? (stbase + nt * 1024) : trash_u;
            stsm_x2_t(addr, h2u(xh[nt][0]), h2u(xh[nt][1]));
        }
        __syncthreads();   // X updated before next layer / emissions
    }

    // emissions: row = q + HALO + 1; read 16B-aligned tile-row chunks
    for (int idx = tid; idx < TT * CS; idx += 256) {
        int t = idx % TT;
        int q = idx / TT;
        int s = s0 + q;
        int row = q + HALO + 1;
        const char* rbase = smem + SM_X + (row >> 3) * 1024 + (row & 7) * 16;
        float acc = ob[t];
        const float* owt = &ow[t * EE];
        #pragma unroll
        for (int c = 0; c < 6; ++c) {
            uint4 v = *(const uint4*)(rbase + c * 128);
            const __half2* hp = (const __half2*)&v;
            #pragma unroll
            for (int m = 0; m < 4; ++m) {
                acc = fmaf(__low2float(hp[m]),  owt[c * 8 + 2 * m],     acc);
                acc = fmaf(__high2float(hp[m]), owt[c * 8 + 2 * m + 1], acc);
            }
        }
        {
            uint32_t v = *(const uint32_t*)(rbase + 6 * 128);
            __half2 h = *(const __half2*)&v;
            acc = fmaf(__low2float(h),  owt[48], acc);
            acc = fmaf(__high2float(h), owt[49], acc);
        }
        int gi = (s * BB + b) * TT + t;
        g_em[gi] = acc;
        g_ee[gi] = __expf(acc);
    }
}

// ===========================================================================
// CRF: grid (BB, 3) x 32 threads. 2-way meet-in-the-middle + deferred renorm.
// ===========================================================================
__device__ __forceinline__ float crf_dot(float c, const float* E)
{
    float a0 = 0.f, a1 = 0.f, a2 = 0.f, a3 = 0.f;
    #pragma unroll
    for (int i = 0; i < TT; i += 4) {
        a0 = fmaf(__shfl_sync(0xffffffffu, c, i + 0), E[i + 0], a0);
        a1 = fmaf(__shfl_sync(0xffffffffu, c, i + 1), E[i + 1], a1);
        a2 = fmaf(__shfl_sync(0xffffffffu, c, i + 2), E[i + 2], a2);
        a3 = fmaf(__shfl_sync(0xffffffffu, c, i + 3), E[i + 3], a3);
    }
    return (a0 + a1) + (a2 + a3);
}

__global__ void crf_kernel(const int* __restrict__ tag,
                           const float* __restrict__ start_trans,
                           const float* __restrict__ end_trans,
                           const float* __restrict__ trans)
{
    const int b = blockIdx.x;
    const int dir = blockIdx.y;
    const int j = threadIdx.x;
    const bool ok = (j < TT);
    const int jj = ok ? j : 0;

    if (dir == 2) {
        float sum = 0.0f;
        for (int s = j; s < SS; s += 32) {
            int tg = tag[b * SS + s];
            sum += g_em[(s * BB + b) * TT + tg];
            if (s > 0)      sum += trans[tag[b * SS + s - 1] * TT + tg];
            if (s == 0)     sum += start_trans[tg];
            if (s == SS-1)  sum += end_trans[tg];
        }
        #pragma unroll
        for (int o = 16; o > 0; o >>= 1) sum += __shfl_xor_sync(0xffffffffu, sum, o);
        if (j == 0) g_num[b] = sum;
        return;
    }

    float E[TT];
    float val, L = 0.0f;
    float ea[8], eb[8];
    float rinv = 1.0f, lg = 0.0f, m;

    if (dir == 0) {
        #pragma unroll
        for (int i = 0; i < TT; ++i) E[i] = ok ? __expf(trans[i * TT + jj]) : 0.0f;
        val = ok ? __expf(start_trans[jj]) * g_ee[(0 * BB + b) * TT + jj] : 0.0f;
        #pragma unroll
        for (int k = 0; k < 8; ++k) ea[k] = g_ee[((1 + k) * BB + b) * TT + jj];
        for (int g = 0; g < 256; g += 2) {
            int t1 = 1 + (g + 1) * 8;
            #pragma unroll
            for (int k = 0; k < 8; ++k) eb[k] = g_ee[((t1 + k) * BB + b) * TT + jj];
            #pragma unroll
            for (int k = 0; k < 8; ++k) val = ea[k] * crf_dot(val, E);
            val *= rinv; L += lg;
            m = __shfl_sync(0xffffffffu, val, 0);
            rinv = __frcp_rn(m); lg = __log2f(m);
            int t2 = 1 + (g + 2) * 8;
            #pragma unroll
            for (int k = 0; k < 8; ++k) ea[k] = g_ee[((t2 + k) * BB + b) * TT + jj];
            #pragma unroll
            for (int k = 0; k < 8; ++k) val = eb[k] * crf_dot(val, E);
            val *= rinv; L += lg;
            m = __shfl_sync(0xffffffffu, val, 0);
            rinv = __frcp_rn(m); lg = __log2f(m);
        }
        val *= rinv; L += lg;
        if (ok) g_fvec[b][jj] = val;
        if (j == 0) g_fL[b] = L;
    } else {
        #pragma unroll
        for (int i = 0; i < TT; ++i) E[i] = ok ? __expf(trans[jj * TT + i]) : 0.0f;
        val = ok ? __expf(end_trans[jj]) : 0.0f;
        #pragma unroll
        for (int k = 0; k < 8; ++k) ea[k] = g_ee[((4095 - k) * BB + b) * TT + jj];
        for (int g = 0; g < 256; g += 2) {
            int m1 = (g + 1) * 8;
            #pragma unroll
            for (int k = 0; k < 8; ++k) {
                int t = 4095 - (m1 + k);
                eb[k] = (t >= 0) ? g_ee[(t * BB + b) * TT + jj] : 0.0f;
            }
            int m0 = g * 8;
            #pragma unroll
            for (int k = 0; k < 8; ++k)
                if (m0 + k < 2047) val = crf_dot(ea[k] * val, E);
            val *= rinv; L += lg;
            m = __shfl_sync(0xffffffffu, val, 0);
            rinv = __frcp_rn(m); lg = __log2f(m);
            int m2 = (g + 2) * 8;
            #pragma unroll
            for (int k = 0; k < 8; ++k) {
                int t = 4095 - (m2 + k);
                ea[k] = (t >= 0) ? g_ee[(t * BB + b) * TT + jj] : 0.0f;
            }
            #pragma unroll
            for (int k = 0; k < 8; ++k)
                if (m1 + k < 2047) val = crf_dot(eb[k] * val, E);
            val *= rinv; L += lg;
            m = __shfl_sync(0xffffffffu, val, 0);
            rinv = __frcp_rn(m); lg = __log2f(m);
        }
        val *= rinv; L += lg;
        if (ok) g_bvec[b][jj] = val;
        if (j == 0) g_bL[b] = L;
    }
}

__global__ void final_kernel(float* __restrict__ out)
{
    __shared__ float red[64];
    int t = threadIdx.x;
    float s = 0.0f;
    #pragma unroll
    for (int i = 0; i < TT; ++i) s += g_fvec[t][i] * g_bvec[t][i];
    float den = (g_fL[t] + g_bL[t]) * 0.69314718055994531f + logf(s);
    red[t] = den - g_num[t];
    __syncthreads();
    for (int k = 32; k > 0; k >>= 1) {
        if (t < k) red[t] += red[t + k];
        __syncthreads();
    }
    if (t == 0) out[0] = red[0];
}

extern "C" void kernel_launch(void* const* d_in, const int* in_sizes, int n_in,
                              void* d_out, int out_size)
{
    const int*   token_id    = (const int*)d_in[0];
    const int*   tag_id      = (const int*)d_in[1];
    const float* embed_table = (const float*)d_in[2];
    const float* conv_w      = (const float*)d_in[3];
    const float* conv_b      = (const float*)d_in[4];
    const float* out_w       = (const float*)d_in[5];
    const float* out_b       = (const float*)d_in[6];
    const float* start_trans = (const float*)d_in[7];
    const float* end_trans   = (const float*)d_in[8];
    const float* trans       = (const float*)d_in[9];

    cudaFuncSetAttribute(conv_emit_kernel,
                         cudaFuncAttributeMaxDynamicSharedMemorySize, SMEM_TOTAL);

    dim3 grid(SS / CS, BB);
    conv_emit_kernel<<<grid, 256, SMEM_TOTAL>>>(token_id, embed_table, conv_w,
                                                conv_b, out_w, out_b);
    crf_kernel<<<dim3(BB, 3), 32>>>(tag_id, start_trans, end_trans, trans);
    final_kernel<<<1, 64>>>((float*)d_out);
}